// round 1
// baseline (speedup 1.0000x reference)
#include <cuda_runtime.h>
#include <math.h>

// Problem constants (fixed shapes from reference setup_inputs)
#define C_DIM  1024   // channels
#define CI_DIM 256    // inter channels
#define B_DIM  16     // batch
#define N_DIM  2048   // H*W = 64*32
#define BN_EPS 1e-5f

// ---------------------------------------------------------------------------
// Static device scratch (no allocation allowed in kernel_launch)
//   theta, phi, g : [B, CI, N]  (32 MB each)
//   S             : [B, N, N]   (256 MB)
//   y             : [B, N, CI]  (32 MB)
// ---------------------------------------------------------------------------
__device__ float g_theta[(size_t)B_DIM * CI_DIM * N_DIM];
__device__ float g_phi  [(size_t)B_DIM * CI_DIM * N_DIM];
__device__ float g_gv   [(size_t)B_DIM * CI_DIM * N_DIM];
__device__ float g_S    [(size_t)B_DIM * N_DIM * N_DIM];
__device__ float g_y    [(size_t)B_DIM * N_DIM * CI_DIM];

// ---------------------------------------------------------------------------
// Common tiling: 64x64 output tile, K-step 16, 256 threads, 4x4 per thread.
// ---------------------------------------------------------------------------
#define TILE   64
#define KSTEP  16
#define NTHR   256

// ===========================================================================
// Kernel 1: input projections.
//   out[b][o, n] = sum_c W[o, c] * x[b, c, n] + bias[o]
//   blockIdx.z = b*3 + p  (p: 0=theta, 1=phi, 2=g)
//   A = W   [CI, C]  row-major (A-style load, transposed into smem)
//   B = x_b [C, N]   row-major (B-style load)
// ===========================================================================
__global__ __launch_bounds__(NTHR)
void proj_kernel(const float* __restrict__ x,
                 const float* __restrict__ tw, const float* __restrict__ tb,
                 const float* __restrict__ pw, const float* __restrict__ pb,
                 const float* __restrict__ gw, const float* __restrict__ gb)
{
    const int b = blockIdx.z / 3;
    const int p = blockIdx.z % 3;
    const float* __restrict__ W    = (p == 0) ? tw : (p == 1) ? pw : gw;
    const float* __restrict__ bias = (p == 0) ? tb : (p == 1) ? pb : gb;
    float* __restrict__ out =
        ((p == 0) ? g_theta : (p == 1) ? g_phi : g_gv) + (size_t)b * CI_DIM * N_DIM;
    const float* __restrict__ Bm = x + (size_t)b * C_DIM * N_DIM;

    __shared__ float As[KSTEP][TILE];
    __shared__ float Bs[KSTEP][TILE];

    const int tid = threadIdx.x;
    const int tx  = tid & 15;     // output col group
    const int ty  = tid >> 4;     // output row group
    const int i0  = blockIdx.y * TILE;
    const int j0  = blockIdx.x * TILE;

    // A-load mapping (row-major [M,K], transpose into As)
    const int ar = tid >> 2;              // 0..63
    const int ak = (tid & 3) << 2;        // 0,4,8,12
    // B-load mapping (row-major [K,N], direct)
    const int br = tid >> 4;              // 0..15
    const int bj = (tid & 15) << 2;       // 0..60

    float acc[4][4] = {};

    for (int k0 = 0; k0 < C_DIM; k0 += KSTEP) {
        float4 av = *(const float4*)&W[(size_t)(i0 + ar) * C_DIM + k0 + ak];
        As[ak + 0][ar] = av.x; As[ak + 1][ar] = av.y;
        As[ak + 2][ar] = av.z; As[ak + 3][ar] = av.w;
        *(float4*)&Bs[br][bj] =
            *(const float4*)&Bm[(size_t)(k0 + br) * N_DIM + j0 + bj];
        __syncthreads();
#pragma unroll
        for (int kk = 0; kk < KSTEP; kk++) {
            float4 a = *(const float4*)&As[kk][ty << 2];
            float4 bb = *(const float4*)&Bs[kk][tx << 2];
            acc[0][0] += a.x * bb.x; acc[0][1] += a.x * bb.y; acc[0][2] += a.x * bb.z; acc[0][3] += a.x * bb.w;
            acc[1][0] += a.y * bb.x; acc[1][1] += a.y * bb.y; acc[1][2] += a.y * bb.z; acc[1][3] += a.y * bb.w;
            acc[2][0] += a.z * bb.x; acc[2][1] += a.z * bb.y; acc[2][2] += a.z * bb.z; acc[2][3] += a.z * bb.w;
            acc[3][0] += a.w * bb.x; acc[3][1] += a.w * bb.y; acc[3][2] += a.w * bb.z; acc[3][3] += a.w * bb.w;
        }
        __syncthreads();
    }

#pragma unroll
    for (int u = 0; u < 4; u++) {
        const int i = i0 + (ty << 2) + u;
        const float bv = bias[i];
        float4 v = make_float4(acc[u][0] + bv, acc[u][1] + bv,
                               acc[u][2] + bv, acc[u][3] + bv);
        *(float4*)&out[(size_t)i * N_DIM + j0 + (tx << 2)] = v;
    }
}

// ===========================================================================
// Kernel 2: attention scores  S[b][n, m] = sum_ci theta[ci, n] * phi[ci, m]
//   Both operands [CI, N], K-major -> both B-style loads.
// ===========================================================================
__global__ __launch_bounds__(NTHR)
void scores_kernel()
{
    const int b = blockIdx.z;
    const float* __restrict__ Q = g_theta + (size_t)b * CI_DIM * N_DIM;
    const float* __restrict__ Kp = g_phi  + (size_t)b * CI_DIM * N_DIM;
    float* __restrict__ S = g_S + (size_t)b * N_DIM * N_DIM;

    __shared__ float As[KSTEP][TILE];
    __shared__ float Bs[KSTEP][TILE];

    const int tid = threadIdx.x;
    const int tx = tid & 15, ty = tid >> 4;
    const int i0 = blockIdx.y * TILE;   // n
    const int j0 = blockIdx.x * TILE;   // m
    const int br = tid >> 4;            // k row 0..15
    const int bj = (tid & 15) << 2;     // col 0..60

    float acc[4][4] = {};

    for (int k0 = 0; k0 < CI_DIM; k0 += KSTEP) {
        *(float4*)&As[br][bj] = *(const float4*)&Q [(size_t)(k0 + br) * N_DIM + i0 + bj];
        *(float4*)&Bs[br][bj] = *(const float4*)&Kp[(size_t)(k0 + br) * N_DIM + j0 + bj];
        __syncthreads();
#pragma unroll
        for (int kk = 0; kk < KSTEP; kk++) {
            float4 a = *(const float4*)&As[kk][ty << 2];
            float4 bb = *(const float4*)&Bs[kk][tx << 2];
            acc[0][0] += a.x * bb.x; acc[0][1] += a.x * bb.y; acc[0][2] += a.x * bb.z; acc[0][3] += a.x * bb.w;
            acc[1][0] += a.y * bb.x; acc[1][1] += a.y * bb.y; acc[1][2] += a.y * bb.z; acc[1][3] += a.y * bb.w;
            acc[2][0] += a.z * bb.x; acc[2][1] += a.z * bb.y; acc[2][2] += a.z * bb.z; acc[2][3] += a.z * bb.w;
            acc[3][0] += a.w * bb.x; acc[3][1] += a.w * bb.y; acc[3][2] += a.w * bb.z; acc[3][3] += a.w * bb.w;
        }
        __syncthreads();
    }

#pragma unroll
    for (int u = 0; u < 4; u++) {
        const int i = i0 + (ty << 2) + u;
        float4 v = make_float4(acc[u][0], acc[u][1], acc[u][2], acc[u][3]);
        *(float4*)&S[(size_t)i * N_DIM + j0 + (tx << 2)] = v;
    }
}

// ===========================================================================
// Kernel 3: row softmax over S (row length N_DIM). One block per row.
// ===========================================================================
__global__ __launch_bounds__(NTHR)
void softmax_kernel()
{
    float* __restrict__ row = g_S + (size_t)blockIdx.x * N_DIM;
    __shared__ float buf[N_DIM];   // 8 KB
    __shared__ float red[8];

    const int tid = threadIdx.x;
    const int lane = tid & 31, warp = tid >> 5;

    float lmax = -INFINITY;
#pragma unroll
    for (int i = tid; i < N_DIM; i += NTHR) {
        float v = row[i];
        buf[i] = v;
        lmax = fmaxf(lmax, v);
    }
#pragma unroll
    for (int o = 16; o; o >>= 1) lmax = fmaxf(lmax, __shfl_xor_sync(0xffffffffu, lmax, o));
    if (lane == 0) red[warp] = lmax;
    __syncthreads();
    float m = red[0];
#pragma unroll
    for (int w = 1; w < 8; w++) m = fmaxf(m, red[w]);
    __syncthreads();

    float lsum = 0.f;
#pragma unroll
    for (int i = tid; i < N_DIM; i += NTHR) {
        float e = __expf(buf[i] - m);
        buf[i] = e;
        lsum += e;
    }
#pragma unroll
    for (int o = 16; o; o >>= 1) lsum += __shfl_xor_sync(0xffffffffu, lsum, o);
    if (lane == 0) red[warp] = lsum;
    __syncthreads();
    float tot = red[0];
#pragma unroll
    for (int w = 1; w < 8; w++) tot += red[w];
    const float inv = 1.f / tot;

#pragma unroll
    for (int i = tid; i < N_DIM; i += NTHR)
        row[i] = buf[i] * inv;
}

// ===========================================================================
// Kernel 4: y[b][n, ci] = sum_m P[b][n, m] * g[b][ci, m]
//   A = P [N, N] row-major     -> A-style load
//   B = g [CI, N] row-major, need B^T -> transposed load into Bs
// ===========================================================================
__global__ __launch_bounds__(NTHR)
void y_kernel()
{
    const int b = blockIdx.z;
    const float* __restrict__ P = g_S  + (size_t)b * N_DIM * N_DIM;
    const float* __restrict__ G = g_gv + (size_t)b * CI_DIM * N_DIM;
    float* __restrict__ Y = g_y + (size_t)b * N_DIM * CI_DIM;

    __shared__ float As[KSTEP][TILE];
    __shared__ float Bs[KSTEP][TILE];

    const int tid = threadIdx.x;
    const int tx = tid & 15, ty = tid >> 4;
    const int i0 = blockIdx.y * TILE;   // n
    const int j0 = blockIdx.x * TILE;   // ci
    const int ar = tid >> 2;            // 0..63
    const int ak = (tid & 3) << 2;      // 0,4,8,12

    float acc[4][4] = {};

    for (int k0 = 0; k0 < N_DIM; k0 += KSTEP) {
        float4 av = *(const float4*)&P[(size_t)(i0 + ar) * N_DIM + k0 + ak];
        As[ak + 0][ar] = av.x; As[ak + 1][ar] = av.y;
        As[ak + 2][ar] = av.z; As[ak + 3][ar] = av.w;
        float4 gv = *(const float4*)&G[(size_t)(j0 + ar) * N_DIM + k0 + ak];
        Bs[ak + 0][ar] = gv.x; Bs[ak + 1][ar] = gv.y;
        Bs[ak + 2][ar] = gv.z; Bs[ak + 3][ar] = gv.w;
        __syncthreads();
#pragma unroll
        for (int kk = 0; kk < KSTEP; kk++) {
            float4 a = *(const float4*)&As[kk][ty << 2];
            float4 bb = *(const float4*)&Bs[kk][tx << 2];
            acc[0][0] += a.x * bb.x; acc[0][1] += a.x * bb.y; acc[0][2] += a.x * bb.z; acc[0][3] += a.x * bb.w;
            acc[1][0] += a.y * bb.x; acc[1][1] += a.y * bb.y; acc[1][2] += a.y * bb.z; acc[1][3] += a.y * bb.w;
            acc[2][0] += a.z * bb.x; acc[2][1] += a.z * bb.y; acc[2][2] += a.z * bb.z; acc[2][3] += a.z * bb.w;
            acc[3][0] += a.w * bb.x; acc[3][1] += a.w * bb.y; acc[3][2] += a.w * bb.z; acc[3][3] += a.w * bb.w;
        }
        __syncthreads();
    }

#pragma unroll
    for (int u = 0; u < 4; u++) {
        const int i = i0 + (ty << 2) + u;
        float4 v = make_float4(acc[u][0], acc[u][1], acc[u][2], acc[u][3]);
        *(float4*)&Y[(size_t)i * CI_DIM + j0 + (tx << 2)] = v;
    }
}

// ===========================================================================
// Kernel 5: z[b][c, n] = sum_ci w_w[c, ci] * y[b][n, ci]  + bias/BN/residual
//   A = w_w [C, CI] row-major  -> A-style load
//   B = y [N, CI] row-major, need B^T -> transposed load
// ===========================================================================
__global__ __launch_bounds__(NTHR)
void out_kernel(const float* __restrict__ x,
                const float* __restrict__ ww, const float* __restrict__ wb,
                const float* __restrict__ gamma, const float* __restrict__ beta,
                const float* __restrict__ mean,  const float* __restrict__ var,
                float* __restrict__ out)
{
    const int b = blockIdx.z;
    const float* __restrict__ Y = g_y + (size_t)b * N_DIM * CI_DIM;

    __shared__ float As[KSTEP][TILE];
    __shared__ float Bs[KSTEP][TILE];

    const int tid = threadIdx.x;
    const int tx = tid & 15, ty = tid >> 4;
    const int i0 = blockIdx.y * TILE;   // c
    const int j0 = blockIdx.x * TILE;   // n
    const int ar = tid >> 2;            // 0..63
    const int ak = (tid & 3) << 2;      // 0,4,8,12

    float acc[4][4] = {};

    for (int k0 = 0; k0 < CI_DIM; k0 += KSTEP) {
        float4 av = *(const float4*)&ww[(size_t)(i0 + ar) * CI_DIM + k0 + ak];
        As[ak + 0][ar] = av.x; As[ak + 1][ar] = av.y;
        As[ak + 2][ar] = av.z; As[ak + 3][ar] = av.w;
        float4 yv = *(const float4*)&Y[(size_t)(j0 + ar) * CI_DIM + k0 + ak];
        Bs[ak + 0][ar] = yv.x; Bs[ak + 1][ar] = yv.y;
        Bs[ak + 2][ar] = yv.z; Bs[ak + 3][ar] = yv.w;
        __syncthreads();
#pragma unroll
        for (int kk = 0; kk < KSTEP; kk++) {
            float4 a = *(const float4*)&As[kk][ty << 2];
            float4 bb = *(const float4*)&Bs[kk][tx << 2];
            acc[0][0] += a.x * bb.x; acc[0][1] += a.x * bb.y; acc[0][2] += a.x * bb.z; acc[0][3] += a.x * bb.w;
            acc[1][0] += a.y * bb.x; acc[1][1] += a.y * bb.y; acc[1][2] += a.y * bb.z; acc[1][3] += a.y * bb.w;
            acc[2][0] += a.z * bb.x; acc[2][1] += a.z * bb.y; acc[2][2] += a.z * bb.z; acc[2][3] += a.z * bb.w;
            acc[3][0] += a.w * bb.x; acc[3][1] += a.w * bb.y; acc[3][2] += a.w * bb.z; acc[3][3] += a.w * bb.w;
        }
        __syncthreads();
    }

#pragma unroll
    for (int u = 0; u < 4; u++) {
        const int c = i0 + (ty << 2) + u;
        const float inv   = gamma[c] * rsqrtf(var[c] + BN_EPS);
        const float shift = beta[c] + (wb[c] - mean[c]) * inv;
        const size_t base = ((size_t)b * C_DIM + c) * N_DIM + j0 + (tx << 2);
        float4 xr = *(const float4*)&x[base];
        float4 v;
        v.x = acc[u][0] * inv + shift + xr.x;
        v.y = acc[u][1] * inv + shift + xr.y;
        v.z = acc[u][2] * inv + shift + xr.z;
        v.w = acc[u][3] * inv + shift + xr.w;
        *(float4*)&out[base] = v;
    }
}

// ===========================================================================
// Launch
// ===========================================================================
extern "C" void kernel_launch(void* const* d_in, const int* in_sizes, int n_in,
                              void* d_out, int out_size)
{
    const float* x       = (const float*)d_in[0];
    const float* theta_w = (const float*)d_in[1];
    const float* theta_b = (const float*)d_in[2];
    const float* phi_w   = (const float*)d_in[3];
    const float* phi_b   = (const float*)d_in[4];
    const float* g_w     = (const float*)d_in[5];
    const float* g_b     = (const float*)d_in[6];
    const float* w_w     = (const float*)d_in[7];
    const float* w_b     = (const float*)d_in[8];
    const float* bn_gamma = (const float*)d_in[9];
    const float* bn_beta  = (const float*)d_in[10];
    const float* bn_mean  = (const float*)d_in[11];
    const float* bn_var   = (const float*)d_in[12];
    float* out = (float*)d_out;

    dim3 blk(NTHR);

    // 1) projections -> theta, phi, g   [B, CI, N]
    proj_kernel<<<dim3(N_DIM / TILE, CI_DIM / TILE, B_DIM * 3), blk>>>(
        x, theta_w, theta_b, phi_w, phi_b, g_w, g_b);

    // 2) S = theta^T phi   [B, N, N]
    scores_kernel<<<dim3(N_DIM / TILE, N_DIM / TILE, B_DIM), blk>>>();

    // 3) row softmax in place
    softmax_kernel<<<B_DIM * N_DIM, NTHR>>>();

    // 4) y = P @ g^T   [B, N, CI]
    y_kernel<<<dim3(CI_DIM / TILE, N_DIM / TILE, B_DIM), blk>>>();

    // 5) z = w_w @ y^T + bias, BN, residual -> out [B, C, N]
    out_kernel<<<dim3(N_DIM / TILE, C_DIM / TILE, B_DIM), blk>>>(
        x, w_w, w_b, bn_gamma, bn_beta, bn_mean, bn_var, out);
}

// round 7
// speedup vs baseline: 2.1270x; 2.1270x over previous
#include <cuda_runtime.h>
#include <cuda_bf16.h>
#include <stdint.h>
#include <math.h>

#define C_DIM  1024
#define CI_DIM 256
#define B_DIM  16
#define N_DIM  2048
#define BN_EPS 1e-5f

typedef __nv_bfloat16 bf16;

// ---------------------------------------------------------------------------
// Static device scratch (hi/lo split-precision planes)
// ---------------------------------------------------------------------------
__device__ bf16 g_xT_hi[(size_t)B_DIM * N_DIM * C_DIM];
__device__ bf16 g_xT_lo[(size_t)B_DIM * N_DIM * C_DIM];
__device__ bf16 g_tw_hi[CI_DIM * C_DIM], g_tw_lo[CI_DIM * C_DIM];
__device__ bf16 g_pw_hi[CI_DIM * C_DIM], g_pw_lo[CI_DIM * C_DIM];
__device__ bf16 g_gw_hi[CI_DIM * C_DIM], g_gw_lo[CI_DIM * C_DIM];
__device__ bf16 g_ww_hi[C_DIM * CI_DIM], g_ww_lo[C_DIM * CI_DIM];
__device__ bf16 g_th_hi[(size_t)B_DIM * N_DIM * CI_DIM], g_th_lo[(size_t)B_DIM * N_DIM * CI_DIM];
__device__ bf16 g_ph_hi[(size_t)B_DIM * N_DIM * CI_DIM], g_ph_lo[(size_t)B_DIM * N_DIM * CI_DIM];
__device__ bf16 g_gv_hi[(size_t)B_DIM * CI_DIM * N_DIM], g_gv_lo[(size_t)B_DIM * CI_DIM * N_DIM];
__device__ float g_S[(size_t)B_DIM * N_DIM * N_DIM];
__device__ bf16 g_P_hi[(size_t)B_DIM * N_DIM * N_DIM], g_P_lo[(size_t)B_DIM * N_DIM * N_DIM];
__device__ bf16 g_y_hi[(size_t)B_DIM * N_DIM * CI_DIM], g_y_lo[(size_t)B_DIM * N_DIM * CI_DIM];

// ---------------------------------------------------------------------------
// PTX helpers (sm_80+ base features only — NO tcgen05, target is sm_103)
// ---------------------------------------------------------------------------
__device__ __forceinline__ uint32_t smem_u32(const void* p) {
    uint32_t a;
    asm("{ .reg .u64 t; cvta.to.shared.u64 t, %1; cvt.u32.u64 %0, t; }" : "=r"(a) : "l"(p));
    return a;
}
__device__ __forceinline__ void cpasync16(uint32_t s, const void* g) {
    asm volatile("cp.async.cg.shared.global [%0], [%1], 16;\n" :: "r"(s), "l"(g));
}
#define CP_COMMIT() asm volatile("cp.async.commit_group;" ::: "memory")
#define CP_WAIT(n)  asm volatile("cp.async.wait_group %0;" :: "n"(n) : "memory")

#define LDSM4(r0, r1, r2, r3, addr) \
    asm volatile("ldmatrix.sync.aligned.m8n8.x4.shared.b16 {%0,%1,%2,%3}, [%4];" \
        : "=r"(r0), "=r"(r1), "=r"(r2), "=r"(r3) : "r"(addr))

#define MMA_BF16(d, a, b) \
    asm volatile("mma.sync.aligned.m16n8k16.row.col.f32.bf16.bf16.f32 " \
        "{%0,%1,%2,%3}, {%4,%5,%6,%7}, {%8,%9}, {%0,%1,%2,%3};" \
        : "+f"((d)[0]), "+f"((d)[1]), "+f"((d)[2]), "+f"((d)[3]) \
        : "r"((a)[0]), "r"((a)[1]), "r"((a)[2]), "r"((a)[3]), "r"((b)[0]), "r"((b)[1]))

// ---------------------------------------------------------------------------
// Generic split-bf16 HMMA GEMM:  D[i,j] = sum_k A[i,k]*B[j,k]
//   A,B K-contiguous hi/lo bf16 planes. CTA tile 128x128, K-chunk 32,
//   2-stage cp.async. 8 warps, warp tile 64x32 (2x4 warp grid).
//   mode 0: bf16 hi/lo out (+optional bias_i[i], bias_j[j]), out[j*ldo+i]
//   mode 1: fp32 out[j*ldo+i]
//   mode 2: fp32 out = D*inv[j] + shift[j] + xres  (BN + residual)
// ---------------------------------------------------------------------------
// Stage layout (bf16, 64B rows, XOR-4 swizzle on 16B chunks):
//   Ah @0, Al @8192, Bh @16384, Bl @24576; stage stride 32768.
#define STAGE_BYTES 32768
#define EPI_PITCH   132                         // fp32 pitch for epilogue staging
#define SMEM_BYTES  (128 * EPI_PITCH * 4 + 512) // 67584+pad >= 2*STAGE_BYTES

__device__ __forceinline__ uint32_t swz(int row, int ch) {
    return (uint32_t)(row * 64 + ((ch ^ (row & 3)) << 4));
}
__device__ __forceinline__ uint32_t ldsm_addr(uint32_t pbase, int rbase, int c0, int lane) {
    const int r = rbase + (lane & 15);
    const int c = c0 + (lane >> 4);
    return pbase + swz(r, c);
}

__device__ __forceinline__ void fill_stage(uint32_t sbase,
    const bf16* __restrict__ Ah, const bf16* __restrict__ Al,
    const bf16* __restrict__ Bh, const bf16* __restrict__ Bl,
    int i0, int j0, int koff, int K)
{
    const int t = threadIdx.x;
#pragma unroll
    for (int rep = 0; rep < 2; rep++) {
        const int e = t + rep * 256;        // 0..511
        const int row = e >> 2;             // 0..127
        const int ch  = e & 3;              // 16B chunk
        const uint32_t so = swz(row, ch);
        const size_t ka = (size_t)(i0 + row) * K + koff + ch * 8;
        const size_t kb = (size_t)(j0 + row) * K + koff + ch * 8;
        cpasync16(sbase + so,                     Ah + ka);
        cpasync16(sbase + 8192 + so,              Al + ka);
        cpasync16(sbase + 16384 + so,             Bh + kb);
        cpasync16(sbase + 24576 + so,             Bl + kb);
    }
}

__global__ __launch_bounds__(256, 1)
void gemm_kernel(const bf16* __restrict__ Ahi, const bf16* __restrict__ Alo,
                 const bf16* __restrict__ Bhi, const bf16* __restrict__ Blo,
                 long long sA, long long sB, int K,
                 bf16* __restrict__ Ohi, bf16* __restrict__ Olo, float* __restrict__ O32,
                 long long sO, int ldo,
                 const float* __restrict__ bias_i, const float* __restrict__ bias_j,
                 int mode,
                 const float* __restrict__ gamma, const float* __restrict__ beta,
                 const float* __restrict__ mean, const float* __restrict__ var,
                 const float* __restrict__ wbias, const float* __restrict__ xres)
{
    extern __shared__ char dsm[];
    const int t = threadIdx.x, lane = t & 31, wid = t >> 5;
    const int wm = wid >> 2, wn = wid & 3;       // 2 x 4 warp grid
    const int b = blockIdx.z;
    const int i0 = blockIdx.y * 128, j0 = blockIdx.x * 128;

    const bf16* Ah = Ahi + (size_t)b * sA;
    const bf16* Al = Alo + (size_t)b * sA;
    const bf16* Bh = Bhi + (size_t)b * sB;
    const bf16* Bl = Blo + (size_t)b * sB;

    const uint32_t sb = smem_u32(dsm);

    float acc[4][4][4] = {};

    const int nk = K >> 5;   // 32-wide K chunks

    fill_stage(sb, Ah, Al, Bh, Bl, i0, j0, 0, K);
    CP_COMMIT();

    for (int k = 0; k < nk; k++) {
        if (k + 1 < nk) {
            fill_stage(sb + ((k + 1) & 1) * STAGE_BYTES, Ah, Al, Bh, Bl, i0, j0, (k + 1) << 5, K);
            CP_COMMIT();
            CP_WAIT(1);
        } else {
            CP_WAIT(0);
        }
        __syncthreads();

        const uint32_t base = sb + (k & 1) * STAGE_BYTES;
#pragma unroll
        for (int ks = 0; ks < 2; ks++) {
            const int c0 = ks * 2;
            uint32_t ah[4][4], al[4][4], bh[4][2], bl[4][2];
#pragma unroll
            for (int mi = 0; mi < 4; mi++) {
                const int rb = wm * 64 + mi * 16;
                LDSM4(ah[mi][0], ah[mi][1], ah[mi][2], ah[mi][3], ldsm_addr(base,        rb, c0, lane));
                LDSM4(al[mi][0], al[mi][1], al[mi][2], al[mi][3], ldsm_addr(base + 8192, rb, c0, lane));
            }
#pragma unroll
            for (int nip = 0; nip < 2; nip++) {
                const int rb = wn * 32 + nip * 16;
                uint32_t r0, r1, r2, r3;
                LDSM4(r0, r1, r2, r3, ldsm_addr(base + 16384, rb, c0, lane));
                bh[nip * 2][0] = r0; bh[nip * 2 + 1][0] = r1;
                bh[nip * 2][1] = r2; bh[nip * 2 + 1][1] = r3;
                LDSM4(r0, r1, r2, r3, ldsm_addr(base + 24576, rb, c0, lane));
                bl[nip * 2][0] = r0; bl[nip * 2 + 1][0] = r1;
                bl[nip * 2][1] = r2; bl[nip * 2 + 1][1] = r3;
            }
#pragma unroll
            for (int mi = 0; mi < 4; mi++)
#pragma unroll
                for (int ni = 0; ni < 4; ni++) {
                    MMA_BF16(acc[mi][ni], ah[mi], bh[ni]);
                    MMA_BF16(acc[mi][ni], ah[mi], bl[ni]);
                    MMA_BF16(acc[mi][ni], al[mi], bh[ni]);
                }
        }
        __syncthreads();
    }

    // ---- epilogue: stage fp32 tile through smem (pitch 132), coalesced out ----
    float* sf = (float*)dsm;
    {
        const int r0 = lane >> 2;
        const int cpair = (lane & 3) << 1;
#pragma unroll
        for (int mi = 0; mi < 4; mi++)
#pragma unroll
            for (int ni = 0; ni < 4; ni++) {
                const int il = wm * 64 + mi * 16 + r0;
                const int jl = wn * 32 + ni * 8 + cpair;
                sf[jl * EPI_PITCH + il]           = acc[mi][ni][0];
                sf[(jl + 1) * EPI_PITCH + il]     = acc[mi][ni][1];
                sf[jl * EPI_PITCH + il + 8]       = acc[mi][ni][2];
                sf[(jl + 1) * EPI_PITCH + il + 8] = acc[mi][ni][3];
            }
    }
    __syncthreads();

#pragma unroll 4
    for (int rep = 0; rep < 64; rep++) {
        const int idx = rep * 256 + t;
        const int jl = idx >> 7, il = idx & 127;
        float v = sf[jl * EPI_PITCH + il];
        const int i = i0 + il;
        const int jg = j0 + jl;
        if (mode == 0) {
            if (bias_i) v += bias_i[i];
            if (bias_j) v += bias_j[jg];
            const bf16 h = __float2bfloat16(v);
            const float lo = v - __bfloat162float(h);
            const size_t a = (size_t)b * sO + (size_t)jg * ldo + i;
            Ohi[a] = h;
            Olo[a] = __float2bfloat16(lo);
        } else if (mode == 1) {
            O32[(size_t)b * sO + (size_t)jg * ldo + i] = v;
        } else {
            const float iv = gamma[jg] * rsqrtf(var[jg] + BN_EPS);
            const float sh = beta[jg] + (wbias[jg] - mean[jg]) * iv;
            const size_t a = (size_t)b * sO + (size_t)jg * ldo + i;
            O32[a] = v * iv + sh + xres[a];
        }
    }
}

// ---------------------------------------------------------------------------
// fp32 -> bf16 hi/lo split (weights)
// ---------------------------------------------------------------------------
__global__ void conv_split(const float* __restrict__ in, bf16* __restrict__ hi,
                           bf16* __restrict__ lo, int n)
{
    int idx = blockIdx.x * 256 + threadIdx.x;
    if (idx < n) {
        float v = in[idx];
        bf16 h = __float2bfloat16(v);
        hi[idx] = h;
        lo[idx] = __float2bfloat16(v - __bfloat162float(h));
    }
}

// ---------------------------------------------------------------------------
// x [B,C,N] fp32 -> xT [B,N,C] bf16 hi/lo  (32x32 smem transpose)
// ---------------------------------------------------------------------------
__global__ __launch_bounds__(256)
void transpose_split(const float* __restrict__ x)
{
    __shared__ float tb[32][33];
    const int b = blockIdx.z;
    const int c0 = blockIdx.y * 32;
    const int n0 = blockIdx.x * 32;
    const int tx = threadIdx.x & 31, ty = threadIdx.x >> 5;
#pragma unroll
    for (int it = 0; it < 4; it++)
        tb[ty + it * 8][tx] = x[((size_t)b * C_DIM + c0 + ty + it * 8) * N_DIM + n0 + tx];
    __syncthreads();
#pragma unroll
    for (int it = 0; it < 4; it++) {
        const float v = tb[tx][ty + it * 8];
        const size_t a = ((size_t)b * N_DIM + n0 + ty + it * 8) * C_DIM + c0 + tx;
        const bf16 h = __float2bfloat16(v);
        g_xT_hi[a] = h;
        g_xT_lo[a] = __float2bfloat16(v - __bfloat162float(h));
    }
}

// ---------------------------------------------------------------------------
// Row softmax: S fp32 [row][2048] -> P hi/lo bf16
// ---------------------------------------------------------------------------
__global__ __launch_bounds__(256)
void softmax_split()
{
    const size_t row = (size_t)blockIdx.x * N_DIM;
    const float* __restrict__ s = g_S + row;
    __shared__ float buf[N_DIM];
    __shared__ float red[8];
    const int tid = threadIdx.x, lane = tid & 31, warp = tid >> 5;

    float lmax = -INFINITY;
#pragma unroll
    for (int it = 0; it < N_DIM / 256; it++) {
        float v = s[tid + it * 256];
        buf[tid + it * 256] = v;
        lmax = fmaxf(lmax, v);
    }
#pragma unroll
    for (int o = 16; o; o >>= 1) lmax = fmaxf(lmax, __shfl_xor_sync(0xffffffffu, lmax, o));
    if (lane == 0) red[warp] = lmax;
    __syncthreads();
    float m = red[0];
#pragma unroll
    for (int w = 1; w < 8; w++) m = fmaxf(m, red[w]);
    __syncthreads();

    float lsum = 0.f;
#pragma unroll
    for (int it = 0; it < N_DIM / 256; it++) {
        float e = __expf(buf[tid + it * 256] - m);
        buf[tid + it * 256] = e;
        lsum += e;
    }
#pragma unroll
    for (int o = 16; o; o >>= 1) lsum += __shfl_xor_sync(0xffffffffu, lsum, o);
    if (lane == 0) red[warp] = lsum;
    __syncthreads();
    float tot = red[0];
#pragma unroll
    for (int w = 1; w < 8; w++) tot += red[w];
    const float inv = 1.f / tot;

#pragma unroll
    for (int it = 0; it < N_DIM / 256; it++) {
        const int idx = tid + it * 256;
        const float p = buf[idx] * inv;
        const bf16 h = __float2bfloat16(p);
        g_P_hi[row + idx] = h;
        g_P_lo[row + idx] = __float2bfloat16(p - __bfloat162float(h));
    }
}

// ---------------------------------------------------------------------------
// Launch
// ---------------------------------------------------------------------------
extern "C" void kernel_launch(void* const* d_in, const int* in_sizes, int n_in,
                              void* d_out, int out_size)
{
    const float* x        = (const float*)d_in[0];
    const float* theta_w  = (const float*)d_in[1];
    const float* theta_b  = (const float*)d_in[2];
    const float* phi_w    = (const float*)d_in[3];
    const float* phi_b    = (const float*)d_in[4];
    const float* g_w      = (const float*)d_in[5];
    const float* g_b      = (const float*)d_in[6];
    const float* w_w      = (const float*)d_in[7];
    const float* w_b      = (const float*)d_in[8];
    const float* bn_gamma = (const float*)d_in[9];
    const float* bn_beta  = (const float*)d_in[10];
    const float* bn_mean  = (const float*)d_in[11];
    const float* bn_var   = (const float*)d_in[12];
    float* out = (float*)d_out;

    cudaFuncSetAttribute(gemm_kernel, cudaFuncAttributeMaxDynamicSharedMemorySize, SMEM_BYTES);

    bf16 *xt_hi, *xt_lo, *tw_hi, *tw_lo, *pw_hi, *pw_lo, *gw_hi, *gw_lo, *ww_hi, *ww_lo;
    bf16 *th_hi, *th_lo, *ph_hi, *ph_lo, *gv_hi, *gv_lo, *P_hi, *P_lo, *y_hi, *y_lo;
    float* Sp;
    cudaGetSymbolAddress((void**)&xt_hi, g_xT_hi); cudaGetSymbolAddress((void**)&xt_lo, g_xT_lo);
    cudaGetSymbolAddress((void**)&tw_hi, g_tw_hi); cudaGetSymbolAddress((void**)&tw_lo, g_tw_lo);
    cudaGetSymbolAddress((void**)&pw_hi, g_pw_hi); cudaGetSymbolAddress((void**)&pw_lo, g_pw_lo);
    cudaGetSymbolAddress((void**)&gw_hi, g_gw_hi); cudaGetSymbolAddress((void**)&gw_lo, g_gw_lo);
    cudaGetSymbolAddress((void**)&ww_hi, g_ww_hi); cudaGetSymbolAddress((void**)&ww_lo, g_ww_lo);
    cudaGetSymbolAddress((void**)&th_hi, g_th_hi); cudaGetSymbolAddress((void**)&th_lo, g_th_lo);
    cudaGetSymbolAddress((void**)&ph_hi, g_ph_hi); cudaGetSymbolAddress((void**)&ph_lo, g_ph_lo);
    cudaGetSymbolAddress((void**)&gv_hi, g_gv_hi); cudaGetSymbolAddress((void**)&gv_lo, g_gv_lo);
    cudaGetSymbolAddress((void**)&P_hi,  g_P_hi);  cudaGetSymbolAddress((void**)&P_lo,  g_P_lo);
    cudaGetSymbolAddress((void**)&y_hi,  g_y_hi);  cudaGetSymbolAddress((void**)&y_lo,  g_y_lo);
    cudaGetSymbolAddress((void**)&Sp,    g_S);

    // 0) weight splits + x transpose/split
    conv_split<<<(CI_DIM * C_DIM + 255) / 256, 256>>>(theta_w, tw_hi, tw_lo, CI_DIM * C_DIM);
    conv_split<<<(CI_DIM * C_DIM + 255) / 256, 256>>>(phi_w,   pw_hi, pw_lo, CI_DIM * C_DIM);
    conv_split<<<(CI_DIM * C_DIM + 255) / 256, 256>>>(g_w,     gw_hi, gw_lo, CI_DIM * C_DIM);
    conv_split<<<(C_DIM * CI_DIM + 255) / 256, 256>>>(w_w,     ww_hi, ww_lo, C_DIM * CI_DIM);
    transpose_split<<<dim3(N_DIM / 32, C_DIM / 32, B_DIM), 256>>>(x);

    const long long sNC  = (long long)N_DIM * C_DIM;
    const long long sNCI = (long long)N_DIM * CI_DIM;
    const long long sCIN = (long long)CI_DIM * N_DIM;
    const long long sNN  = (long long)N_DIM * N_DIM;
    const long long sCN  = (long long)C_DIM * N_DIM;

    // 1) theta: D[o,n] = sum_c tw[o,c] * xT[n,c]  -> th [B,N,CI]
    gemm_kernel<<<dim3(N_DIM / 128, CI_DIM / 128, B_DIM), 256, SMEM_BYTES>>>(
        tw_hi, tw_lo, xt_hi, xt_lo, 0, sNC, C_DIM,
        th_hi, th_lo, nullptr, sNCI, CI_DIM, theta_b, nullptr, 0,
        nullptr, nullptr, nullptr, nullptr, nullptr, nullptr);
    // 2) phi
    gemm_kernel<<<dim3(N_DIM / 128, CI_DIM / 128, B_DIM), 256, SMEM_BYTES>>>(
        pw_hi, pw_lo, xt_hi, xt_lo, 0, sNC, C_DIM,
        ph_hi, ph_lo, nullptr, sNCI, CI_DIM, phi_b, nullptr, 0,
        nullptr, nullptr, nullptr, nullptr, nullptr, nullptr);
    // 3) g: D[n,ci] = sum_c xT[n,c] * gw[ci,c]  -> gv [B,CI,N]
    gemm_kernel<<<dim3(CI_DIM / 128, N_DIM / 128, B_DIM), 256, SMEM_BYTES>>>(
        xt_hi, xt_lo, gw_hi, gw_lo, sNC, 0, C_DIM,
        gv_hi, gv_lo, nullptr, sCIN, N_DIM, nullptr, g_b, 0,
        nullptr, nullptr, nullptr, nullptr, nullptr, nullptr);
    // 4) S: D[m,n] = sum_ci phi[m,ci] * theta[n,ci]  -> S fp32 [B,N,N]
    gemm_kernel<<<dim3(N_DIM / 128, N_DIM / 128, B_DIM), 256, SMEM_BYTES>>>(
        ph_hi, ph_lo, th_hi, th_lo, sNCI, sNCI, CI_DIM,
        nullptr, nullptr, Sp, sNN, N_DIM, nullptr, nullptr, 1,
        nullptr, nullptr, nullptr, nullptr, nullptr, nullptr);
    // 5) softmax rows -> P hi/lo
    softmax_split<<<B_DIM * N_DIM, 256>>>();
    // 6) y: D[ci,n] = sum_m gv[ci,m] * P[n,m]  -> y [B,N,CI]
    gemm_kernel<<<dim3(N_DIM / 128, CI_DIM / 128, B_DIM), 256, SMEM_BYTES>>>(
        gv_hi, gv_lo, P_hi, P_lo, sCIN, sNN, N_DIM,
        y_hi, y_lo, nullptr, sNCI, CI_DIM, nullptr, nullptr, 0,
        nullptr, nullptr, nullptr, nullptr, nullptr, nullptr);
    // 7) out: D[n,c] = sum_ci y[n,ci] * ww[c,ci], BN + residual
    gemm_kernel<<<dim3(C_DIM / 128, N_DIM / 128, B_DIM), 256, SMEM_BYTES>>>(
        y_hi, y_lo, ww_hi, ww_lo, sNCI, 0, CI_DIM,
        nullptr, nullptr, out, sCN, N_DIM, nullptr, nullptr, 2,
        bn_gamma, bn_beta, bn_mean, bn_var, w_b, x);
}